// round 10
// baseline (speedup 1.0000x reference)
#include <cuda_runtime.h>
#include <math.h>

#define N_CELLS 8192
#define HID 128
#define IN_DIM 64
#define OUT_DIM 64
#define NFAC 8
#define FS 1024
#define TOPK 8
#define NCAP 256
#define FMAX 3.402823466e38f

// padded row stride (floats) for smem weight matrices: 128 + 4 kills the
// 32-way bank conflict (row offset rotates 4 banks per row)
#define WST 132

// dynamic smem layout (floats)
#define SW1A_OFF 0
#define SW1G_OFF (128 * WST)            // 16896
#define SB_OFF   (2 * 128 * WST)        // 33792 : edges/ages, later w2a/w2g
#define SB_FLOATS (2 * 64 * WST)        // 16896 (>= 16384 needed for edges+ages)
#define DYN_FLOATS (SB_OFF + SB_FLOATS) // 50688
#define DYN_BYTES (DYN_FLOATS * 4)      // 202752

__device__ __align__(16) float g_dists[N_CELLS];
__device__ __align__(16) float g_fpart[128 * HID];

__device__ __forceinline__ unsigned su32(const void* p) {
    return (unsigned)__cvta_generic_to_shared(p);
}
#define CPA16(dst, src) \
    asm volatile("cp.async.cg.shared.global [%0], [%1], 16;\n" :: "r"(dst), "l"(src))
#define CPA_COMMIT() asm volatile("cp.async.commit_group;\n")
#define CPA_WAIT0()  asm volatile("cp.async.wait_group 0;\n")

// ---------------------------------------------------------------------------
// K1: signal (recomputed) + per-row squared distances + per-block proto sums
// ---------------------------------------------------------------------------
__global__ void __launch_bounds__(256)
k_dists(const float* __restrict__ x,
        const float* __restrict__ in_w,
        const float* __restrict__ in_b,
        const float* __restrict__ proto) {
    __shared__ __align__(16) float ssig[HID];
    __shared__ float sfs_w[8][HID];
    int tid = threadIdx.x, wid = tid >> 5, lane = tid & 31;

    if (tid < HID) {
        float acc = in_b[tid];
        const float4* w4 = (const float4*)(in_w + tid * IN_DIM);
        const float4* x4 = (const float4*)x;
#pragma unroll
        for (int i = 0; i < IN_DIM / 4; ++i) {
            float4 wv = w4[i], xv = x4[i];
            acc += wv.x * xv.x + wv.y * xv.y + wv.z * xv.z + wv.w * xv.w;
        }
        ssig[tid] = acc;
    }
    __syncthreads();

    int d0 = lane * 4;
    float s0 = ssig[d0], s1 = ssig[d0 + 1], s2 = ssig[d0 + 2], s3 = ssig[d0 + 3];
    float ax = 0.f, ay = 0.f, az = 0.f, aw = 0.f;
    int row0 = blockIdx.x * 64;
#pragma unroll
    for (int p = 0; p < 8; ++p) {
        int row = row0 + p * 8 + wid;
        float4 a = ((const float4*)(proto + (size_t)row * HID))[lane];
        ax += a.x; ay += a.y; az += a.z; aw += a.w;
        float dx = a.x - s0, dy = a.y - s1, dz = a.z - s2, dw = a.w - s3;
        float s = dx * dx + dy * dy + dz * dz + dw * dw;
#pragma unroll
        for (int off = 16; off; off >>= 1) s += __shfl_down_sync(0xffffffffu, s, off);
        if (lane == 0) g_dists[row] = s;
    }
    ((float4*)&sfs_w[wid][d0])[0] = make_float4(ax, ay, az, aw);
    __syncthreads();
    if (tid < HID) {
        float t = 0.f;
#pragma unroll
        for (int w = 0; w < 8; ++w) t += sfs_w[w][tid];
        g_fpart[blockIdx.x * HID + tid] = t;
    }
}

// ---------------------------------------------------------------------------
// K2: everything else; one block of 1024 threads, heavy prefetch overlap
// ---------------------------------------------------------------------------
extern __shared__ float dyn[];

__global__ void __launch_bounds__(1024, 1)
k_main(const float* __restrict__ x,
       const float* __restrict__ in_w,
       const float* __restrict__ in_b,
       const float* __restrict__ proto,
       const float* __restrict__ edges,
       const float* __restrict__ eages,
       const int* __restrict__ stepp,
       const float* __restrict__ out_w, const float* __restrict__ out_b,
       const float* __restrict__ ea_w1, const float* __restrict__ ea_b1,
       const float* __restrict__ ea_w2, const float* __restrict__ ea_b2,
       const float* __restrict__ eg_w1, const float* __restrict__ eg_b1,
       const float* __restrict__ eg_w2, const float* __restrict__ eg_b2,
       float* __restrict__ out) {
    __shared__ __align__(16) float ssig[HID];
    __shared__ float fsum[NFAC][HID];
    __shared__ float dsum[NFAC][HID];
    __shared__ float fmean[NFAC][HID];
    __shared__ __align__(16) float sproto[TOPK][HID];
    __shared__ __align__(16) float p1s[HID], p2s[HID];
    __shared__ __align__(16) float win[HID];
    __shared__ __align__(16) float comb[HID];
    __shared__ __align__(16) float h1[HID], h2[HID];
    __shared__ __align__(16) float s_b1a[HID], s_b1g[HID];
    __shared__ __align__(16) float s_b2a[OUT_DIM], s_b2g[OUT_DIM], s_ob[OUT_DIM];
    __shared__ float candd[256];
    __shared__ int   candi[256];
    __shared__ int   topi[TOPK];
    __shared__ float topd[TOPK];
    __shared__ float w8raw[TOPK];
    __shared__ float rd[8];
    __shared__ unsigned char nmask8[N_CELLS / 8];   // bitmask, byte per thread
    __shared__ int nlist[NCAP];
    __shared__ int cnt[NFAC];
    __shared__ int ncount;
    __shared__ unsigned long long s_min;

    float* sw1a = dyn + SW1A_OFF;
    float* sw1g = dyn + SW1G_OFF;
    float* sB   = dyn + SB_OFF;

    int tid = threadIdx.x;
    int lane = tid & 31, wid = tid >> 5;
    int ff = tid >> 7, dd = tid & 127;

    int step = stepp[0];
    float epsw = 0.3f * expf(-(float)step / 200.0f);
    if (epsw < 0.05f) epsw = 0.05f;
    float epsn = epsw * 0.01f;
    bool debate = step > 5;

    // ---- entry: async prefetch of MLP1 weights (padded rows) + biases ----
    {
        const float4* s1 = (const float4*)ea_w1;
        const float4* s2 = (const float4*)eg_w1;
        unsigned d1 = su32(sw1a), d2 = su32(sw1g);
#pragma unroll
        for (int i = 0; i < 4; ++i) {
            int t = tid + i * 1024;                 // f4 index in 128x32
            unsigned doff = (unsigned)(((t >> 5) * 33 + (t & 31)) * 16);
            CPA16(d1 + doff, s1 + t);
            CPA16(d2 + doff, s2 + t);
        }
        if (tid < 32)       CPA16(su32(s_b1a) + tid * 16, (const float4*)ea_b1 + tid);
        else if (tid < 64)  CPA16(su32(s_b1g) + (tid - 32) * 16, (const float4*)eg_b1 + (tid - 32));
        else if (tid < 80)  CPA16(su32(s_b2a) + (tid - 64) * 16, (const float4*)ea_b2 + (tid - 64));
        else if (tid < 96)  CPA16(su32(s_b2g) + (tid - 80) * 16, (const float4*)eg_b2 + (tid - 80));
        else if (tid < 112) CPA16(su32(s_ob) + (tid - 96) * 16, (const float4*)out_b + (tid - 96));
        CPA_COMMIT();
    }

    // ---- signal, fsum reduction, init ----
    if (tid < HID) {
        float acc = in_b[tid];
        const float4* w4 = (const float4*)(in_w + tid * IN_DIM);
        const float4* x4 = (const float4*)x;
#pragma unroll
        for (int i = 0; i < IN_DIM / 4; ++i) {
            float4 wv = w4[i], xv = x4[i];
            acc += wv.x * xv.x + wv.y * xv.y + wv.z * xv.z + wv.w * xv.w;
        }
        ssig[tid] = acc;
    }
    {
        float t = 0.f;
#pragma unroll
        for (int b = 0; b < 16; ++b) t += g_fpart[(ff * 16 + b) * HID + dd];
        fsum[ff][dd] = t;
        dsum[ff][dd] = 0.f;
    }
    if (tid < NFAC) cnt[tid] = 0;
    if (tid == 0) { ncount = 0; s_min = 0xFFFFFFFFFFFFFFFFull; }

    // load this thread's 8 dists
    float dv[8];
    {
        int base = wid * 256 + lane * 8;
        const float4* dp = (const float4*)(g_dists + base);
        float4 a = dp[0], b = dp[1];
        dv[0] = a.x; dv[1] = a.y; dv[2] = a.z; dv[3] = a.w;
        dv[4] = b.x; dv[5] = b.y; dv[6] = b.z; dv[7] = b.w;
    }
    __syncthreads();   // B0: s_min/cnt init visible

    int base = wid * 256 + lane * 8;

    // ---- selection round 0 + global argmin via packed atomicMin ----
    {
        float lb = dv[0]; int li = 0;
#pragma unroll
        for (int i = 1; i < 8; ++i)
            if (dv[i] < lb) { lb = dv[i]; li = i; }
        int gi = base + li;
        float wd = lb; int wi = gi;
#pragma unroll
        for (int off = 16; off; off >>= 1) {
            float od = __shfl_xor_sync(0xffffffffu, wd, off);
            int   oi = __shfl_xor_sync(0xffffffffu, wi, off);
            if (od < wd || (od == wd && oi < wi)) { wd = od; wi = oi; }
        }
        if (wi == gi) dv[li] = FMAX;
        if (lane == 0) {
            candd[wid * 8] = wd; candi[wid * 8] = wi;
            unsigned long long key =
                ((unsigned long long)__float_as_uint(wd) << 32) | (unsigned)wi;
            atomicMin(&s_min, key);
        }
    }
    __syncthreads();   // B1: s_min final

    // ---- early edge/age prefetch for b1 (exact: matches final topi[0]) ----
    {
        int b1e = (int)(s_min & 0xFFFFFFFFull);
        const float4* es = (const float4*)(edges + (size_t)b1e * N_CELLS);
        const float4* as = (const float4*)(eages + (size_t)b1e * N_CELLS);
        unsigned de = su32(sB), da = su32(sB) + 32768u;
#pragma unroll
        for (int i = 0; i < 2; ++i) {
            int t = tid + i * 1024;
            CPA16(de + (unsigned)t * 16, es + t);
            CPA16(da + (unsigned)t * 16, as + t);
        }
        CPA_COMMIT();
    }

    // ---- selection rounds 1..7 (per-warp top-8) ----
#pragma unroll
    for (int k = 1; k < TOPK; ++k) {
        float lb = dv[0]; int li = 0;
#pragma unroll
        for (int i = 1; i < 8; ++i)
            if (dv[i] < lb) { lb = dv[i]; li = i; }
        int gi = base + li;
        float wd = lb; int wi = gi;
#pragma unroll
        for (int off = 16; off; off >>= 1) {
            float od = __shfl_xor_sync(0xffffffffu, wd, off);
            int   oi = __shfl_xor_sync(0xffffffffu, wi, off);
            if (od < wd || (od == wd && oi < wi)) { wd = od; wi = oi; }
        }
        if (wi == gi) dv[li] = FMAX;
        if (lane == k) { candd[wid * 8 + k] = wd; candi[wid * 8 + k] = wi; }
    }
    CPA_WAIT0();       // own groups done (w1 + edges long in flight)
    __syncthreads();   // B2: candd/candi + all cp.async data visible

    // ---- stage-2: warp 0 selects global top-8 ----
    if (wid == 0) {
        float sv[8]; int iv[8];
#pragma unroll
        for (int i = 0; i < 8; ++i) { sv[i] = candd[lane * 8 + i]; iv[i] = candi[lane * 8 + i]; }
#pragma unroll
        for (int k = 0; k < TOPK; ++k) {
            float lb = sv[0]; int li = 0;
#pragma unroll
            for (int i = 1; i < 8; ++i)
                if (sv[i] < lb || (sv[i] == lb && iv[i] < iv[li])) { lb = sv[i]; li = i; }
            float wd = lb; int wi = iv[li];
#pragma unroll
            for (int off = 16; off; off >>= 1) {
                float od = __shfl_xor_sync(0xffffffffu, wd, off);
                int   oi = __shfl_xor_sync(0xffffffffu, wi, off);
                if (od < wd || (od == wd && oi < wi)) { wd = od; wi = oi; }
            }
            if (wi == iv[li]) sv[li] = FMAX;
            if (lane == k) { topd[k] = wd; topi[k] = wi; }
        }
    }
    __syncthreads();   // B3: topi/topd final

    const int b1 = topi[0], b2 = topi[1];

    // ---- issue top-8 proto row prefetch (consumed after B4) ----
    float pv_pref = proto[(size_t)topi[ff] * HID + dd];

    // ---- edge/age processing from smem ----
    {
        int j0 = tid * 8;
        float4 e0 = ((const float4*)sB)[tid * 2];
        float4 e1 = ((const float4*)sB)[tid * 2 + 1];
        float4 a0 = ((const float4*)(sB + 8192))[tid * 2];
        float4 a1 = ((const float4*)(sB + 8192))[tid * 2 + 1];
        float ev[8] = { e0.x, e0.y, e0.z, e0.w, e1.x, e1.y, e1.z, e1.w };
        float ag[8] = { a0.x, a0.y, a0.z, a0.w, a1.x, a1.y, a1.z, a1.w };
        unsigned char bits = 0;
#pragma unroll
        for (int i = 0; i < 8; ++i) {
            int j = j0 + i;
            float e = ev[i], a = ag[i];
            if (j == b2) { e = 1.f; a = 0.f; }
            a += 1.f;
            if (j == b1) a += 1.f;          // row add + col add hit diagonal
            bool nm = (a <= 50.f) && (e > 0.f);
            if (nm) bits |= (unsigned char)(1 << i);
            if (nm && j != b1 && j != b2) {
                atomicAdd(&cnt[j >> 10], 1);
                int pos = atomicAdd(&ncount, 1);
                if (pos < NCAP) nlist[pos] = j;
                else {   // overflow fallback (correct, slow, pathological only)
                    const float* pr = proto + (size_t)j * HID;
                    for (int d = 0; d < HID; ++d) atomicAdd(&dsum[j >> 10][d], pr[d]);
                }
            }
        }
        nmask8[tid] = bits;
    }
    if (tid < TOPK) w8raw[tid] = expf(-(topd[tid] - topd[0]));
    sproto[ff][dd] = pv_pref;
    __syncthreads();   // B4: nmask/nlist/sproto ready

    // ---- issue w2 prefetch into region B (edges consumed) ----
    {
        const float4* s3 = (const float4*)ea_w2;
        const float4* s4 = (const float4*)eg_w2;
        unsigned d3 = su32(sB), d4 = su32(sB) + (unsigned)(64 * WST * 4);
#pragma unroll
        for (int i = 0; i < 2; ++i) {
            int t = tid + i * 1024;                 // f4 index in 64x32
            unsigned doff = (unsigned)(((t >> 5) * 33 + (t & 31)) * 16);
            CPA16(d3 + doff, s3 + t);
            CPA16(d4 + doff, s4 + t);
        }
        CPA_COMMIT();
    }

    // ---- neighbor proto gather + bmu row updates ----
    {
        int n = ncount < NCAP ? ncount : NCAP;
        for (int e = ff; e < n; e += NFAC) {
            int j = nlist[e];
            atomicAdd(&dsum[j >> 10][dd], proto[(size_t)j * HID + dd]);
        }
    }
    if (tid < HID) {
        int d = tid;
        float s = ssig[d];
        bool m1 = (nmask8[b1 >> 3] >> (b1 & 7)) & 1;
        bool m2 = (nmask8[b2 >> 3] >> (b2 & 7)) & 1;
        float p1 = sproto[0][d];
        float v1 = p1 + epsw * (s - p1);
        if (m1) v1 = v1 + epsn * (s - v1);
        p1s[d] = v1;
        float p2 = sproto[1][d];
        float v2 = p2 + epsn * (s - p2);
        if (m2) v2 = v2 + epsn * (s - v2);
        p2s[d] = v2;
    }
    __syncthreads();   // B5

    // ---- faction means ----
    {
        float adj = epsn * (ssig[dd] * (float)cnt[ff] - dsum[ff][dd]);
        if ((b1 >> 10) == ff) adj += p1s[dd] - sproto[0][dd];
        if ((b2 >> 10) == ff) adj += p2s[dd] - sproto[1][dd];
        fmean[ff][dd] = (fsum[ff][dd] + adj) * (1.0f / FS);
    }
    __syncthreads();   // B6

    // ---- winner row (tids 0-127) + weighted combine (tids 128-255) ----
    if (tid < HID) {
        float g = 0.f;
#pragma unroll
        for (int f = 0; f < NFAC; ++f) g += fmean[f][tid];
        g *= (1.0f / NFAC);
        float v = 0.85f * p1s[tid] + 0.15f * fmean[b1 >> 10][tid];
        if (debate && (b1 & (FS - 1)) < 256) v = 0.85f * v + 0.15f * g;
        win[tid] = v;
    } else if (tid < 256) {
        int d = tid - 128;
        float g = 0.f;
#pragma unroll
        for (int f = 0; f < NFAC; ++f) g += fmean[f][d];
        g *= (1.0f / NFAC);
        float wsum = 0.f;
#pragma unroll
        for (int k = 0; k < TOPK; ++k) wsum += w8raw[k];
        float inv = 1.0f / wsum;
        float acc = 0.f;
#pragma unroll
        for (int k = 0; k < TOPK; ++k) {
            int i = topi[k];
            float pv;
            if (k == 0)      pv = p1s[d];
            else if (k == 1) pv = p2s[d];
            else {
                pv = sproto[k][d];
                if ((nmask8[i >> 3] >> (i & 7)) & 1) pv = pv + epsn * (ssig[d] - pv);
            }
            float v = 0.85f * pv + 0.15f * fmean[i >> 10][d];
            if (debate && (i & (FS - 1)) < 256) v = 0.85f * v + 0.15f * g;
            acc += w8raw[k] * v;
        }
        comb[d] = acc * inv;
    }
    __syncthreads();   // B7: win/comb ready

    // ---- MLP1: 256 outputs x 4 threads, smem weights ----
    {
        int o = tid >> 2, q = tid & 3;
        const float* wrow = (o < 128 ? sw1a + o * WST : sw1g + (o - 128) * WST) + q * 32;
        const float4* w4 = (const float4*)wrow;
        const float4* v4 = (const float4*)(win + q * 32);
        float acc = 0.f;
#pragma unroll
        for (int i = 0; i < 8; ++i) {
            float4 a = w4[i], b = v4[i];
            acc += a.x * b.x + a.y * b.y + a.z * b.z + a.w * b.w;
        }
        acc += __shfl_down_sync(0xffffffffu, acc, 1);
        acc += __shfl_down_sync(0xffffffffu, acc, 2);
        if (q == 0) {
            if (o < 128) { float v = acc + s_b1a[o]; h1[o] = v > 0.f ? v : 0.f; }
            else         { float v = acc + s_b1g[o - 128]; h2[o - 128] = v > 0.f ? v : 0.f; }
        }
    }
    CPA_WAIT0();       // w2 groups done
    __syncthreads();   // B8: h1/h2 + w2 smem visible

    // ---- MLP2: tension (groups 0-63) + final output (groups 64-127) ----
    {
        int o = tid >> 2, q = tid & 3;
        float t = 0.f;
        if (o < 64) {
            const float4* wa = (const float4*)(sB + o * WST + q * 32);
            const float4* wg = (const float4*)(sB + 64 * WST + o * WST + q * 32);
            const float4* v1 = (const float4*)(h1 + q * 32);
            const float4* v2 = (const float4*)(h2 + q * 32);
            float a = 0.f, g = 0.f;
#pragma unroll
            for (int i = 0; i < 8; ++i) {
                float4 xa = wa[i], xg = wg[i], y1 = v1[i], y2 = v2[i];
                a += xa.x * y1.x + xa.y * y1.y + xa.z * y1.z + xa.w * y1.w;
                g += xg.x * y2.x + xg.y * y2.y + xg.z * y2.z + xg.w * y2.w;
            }
            a += __shfl_xor_sync(0xffffffffu, a, 1);
            a += __shfl_xor_sync(0xffffffffu, a, 2);
            g += __shfl_xor_sync(0xffffffffu, g, 1);
            g += __shfl_xor_sync(0xffffffffu, g, 2);
            if (q == 0) {
                float diff = (a + s_b2a[o]) - (g + s_b2g[o]);
                t = diff * diff;
            }
        } else if (o < 128) {
            int r = o - 64;
            const float4* wo = (const float4*)(out_w + r * HID) + q * 8;
            const float4* c4 = (const float4*)(comb + q * 32);
            float acc = 0.f;
#pragma unroll
            for (int i = 0; i < 8; ++i) {
                float4 a = wo[i], b = c4[i];
                acc += a.x * b.x + a.y * b.y + a.z * b.z + a.w * b.w;
            }
            acc += __shfl_down_sync(0xffffffffu, acc, 1);
            acc += __shfl_down_sync(0xffffffffu, acc, 2);
            if (q == 0) out[r] = acc + s_ob[r];
        }
        // warp-reduce tension contributions (warps 0-7 only have nonzero t)
#pragma unroll
        for (int off = 16; off; off >>= 1)
            t += __shfl_down_sync(0xffffffffu, t, off);
        if (lane == 0 && wid < 8) rd[wid] = t;
    }
    __syncthreads();   // B9
    if (tid == 0) {
        float s = 0.f;
#pragma unroll
        for (int i = 0; i < 8; ++i) s += rd[i];
        out[OUT_DIM] = s * (1.0f / 64.0f);
    }
}

// ---------------------------------------------------------------------------
extern "C" void kernel_launch(void* const* d_in, const int* in_sizes, int n_in,
                              void* d_out, int out_size) {
    const float* x      = (const float*)d_in[0];
    const int*   step   = (const int*)  d_in[1];
    const float* proto  = (const float*)d_in[2];
    const float* edges  = (const float*)d_in[3];
    const float* eages  = (const float*)d_in[4];
    const float* in_w   = (const float*)d_in[5];
    const float* in_b   = (const float*)d_in[6];
    const float* out_w  = (const float*)d_in[7];
    const float* out_b  = (const float*)d_in[8];
    const float* ea_w1  = (const float*)d_in[9];
    const float* ea_b1  = (const float*)d_in[10];
    const float* ea_w2  = (const float*)d_in[11];
    const float* ea_b2  = (const float*)d_in[12];
    const float* eg_w1  = (const float*)d_in[13];
    const float* eg_b1  = (const float*)d_in[14];
    const float* eg_w2  = (const float*)d_in[15];
    const float* eg_b2  = (const float*)d_in[16];
    float* out = (float*)d_out;

    cudaFuncSetAttribute(k_main, cudaFuncAttributeMaxDynamicSharedMemorySize,
                         DYN_BYTES);

    k_dists<<<128, 256>>>(x, in_w, in_b, proto);
    k_main<<<1, 1024, DYN_BYTES>>>(x, in_w, in_b, proto, edges, eages, step,
                                   out_w, out_b,
                                   ea_w1, ea_b1, ea_w2, ea_b2,
                                   eg_w1, eg_b1, eg_w2, eg_b2,
                                   out);
}

// round 14
// speedup vs baseline: 1.0872x; 1.0872x over previous
#include <cuda_runtime.h>
#include <math.h>

#define N_CELLS 8192
#define HID 128
#define IN_DIM 64
#define OUT_DIM 64
#define NFAC 8
#define FS 1024
#define TOPK 8
#define NBLK 32
#define ROWS_PER_BLK 256
#define NCAP 4096
#define FMAX 3.402823466e38f

__device__ __align__(16) float g_fpart[NBLK * HID];
__device__ __align__(16) float g_cand_d[NBLK * TOPK];
__device__ int g_cand_i[NBLK * TOPK];
__device__ unsigned g_arrive;

// ---------------------------------------------------------------------------
// Single fused kernel: 32 blocks x 1024 threads.
// Phase A (all blocks): signal, dists, faction partial sums, per-block top-8.
// Software grid barrier (only block 0 waits -> deadlock-free).
// Phase B (block 0): selection stage-2, edges, updates, MLPs, output.
// ---------------------------------------------------------------------------
__global__ void __launch_bounds__(1024, 1)
k_all(const float* __restrict__ x,
      const float* __restrict__ in_w,
      const float* __restrict__ in_b,
      const float* __restrict__ proto,
      const float* __restrict__ edges,
      const float* __restrict__ eages,
      const int* __restrict__ stepp,
      const float* __restrict__ out_w, const float* __restrict__ out_b,
      const float* __restrict__ ea_w1, const float* __restrict__ ea_b1,
      const float* __restrict__ ea_w2, const float* __restrict__ ea_b2,
      const float* __restrict__ eg_w1, const float* __restrict__ eg_b1,
      const float* __restrict__ eg_w2, const float* __restrict__ eg_b2,
      float* __restrict__ out) {
    // pool: phase A = per-warp faction sums [32][128]; phase B = nlist[4096]
    __shared__ __align__(16) float pool[NBLK * HID];
    __shared__ __align__(16) float sd[ROWS_PER_BLK];
    __shared__ __align__(16) float ssig[HID];
    __shared__ float fsum[NFAC][HID];
    __shared__ float dsum[NFAC][HID];
    __shared__ float fmean[NFAC][HID];
    __shared__ __align__(16) float sproto[TOPK][HID];
    __shared__ __align__(16) float p1s[HID], p2s[HID];
    __shared__ __align__(16) float win[HID];
    __shared__ __align__(16) float comb[HID];
    __shared__ __align__(16) float h1[HID], h2[HID];
    __shared__ int   topi[TOPK];
    __shared__ float topd[TOPK];
    __shared__ float w8raw[TOPK];
    __shared__ float rd[8];
    __shared__ unsigned char nmask8[N_CELLS / 8];
    __shared__ int cnt[NFAC];
    __shared__ int ncount;

    int tid = threadIdx.x;
    int lane = tid & 31, wid = tid >> 5;
    int blk = blockIdx.x;

    // ================= PHASE A (all 32 blocks) =================
    if (tid < HID) {
        float acc = in_b[tid];
        const float4* w4 = (const float4*)(in_w + tid * IN_DIM);
        const float4* x4 = (const float4*)x;
#pragma unroll
        for (int i = 0; i < IN_DIM / 4; ++i) {
            float4 wv = w4[i], xv = x4[i];
            acc += wv.x * xv.x + wv.y * xv.y + wv.z * xv.z + wv.w * xv.w;
        }
        ssig[tid] = acc;
    }
    __syncthreads();

    {
        int d0 = lane * 4;
        float s0 = ssig[d0], s1 = ssig[d0 + 1], s2 = ssig[d0 + 2], s3 = ssig[d0 + 3];
        float ax = 0.f, ay = 0.f, az = 0.f, aw = 0.f;
        int row0 = blk * ROWS_PER_BLK + wid * 8;
#pragma unroll
        for (int p = 0; p < 8; ++p) {
            int row = row0 + p;
            float4 a = ((const float4*)(proto + (size_t)row * HID))[lane];
            ax += a.x; ay += a.y; az += a.z; aw += a.w;
            float dx = a.x - s0, dy = a.y - s1, dz = a.z - s2, dw = a.w - s3;
            float s = dx * dx + dy * dy + dz * dz + dw * dw;
#pragma unroll
            for (int off = 16; off; off >>= 1)
                s += __shfl_down_sync(0xffffffffu, s, off);
            if (lane == 0) sd[wid * 8 + p] = s;
        }
        ((float4*)(pool + wid * HID + d0))[0] = make_float4(ax, ay, az, aw);
    }
    __syncthreads();

    // warps 4-7: reduce faction partial sums -> g_fpart[blk]
    if (tid >= 128 && tid < 256) {
        int d = tid - 128;
        float t = 0.f;
#pragma unroll
        for (int w = 0; w < 32; ++w) t += pool[w * HID + d];
        g_fpart[blk * HID + d] = t;
    }
    // warp 0: per-block top-8 candidates -> g_cand
    if (wid == 0) {
        int base = lane * 8;
        float dv[8];
        const float4* dp = (const float4*)(sd + base);
        float4 a = dp[0], b = dp[1];
        dv[0] = a.x; dv[1] = a.y; dv[2] = a.z; dv[3] = a.w;
        dv[4] = b.x; dv[5] = b.y; dv[6] = b.z; dv[7] = b.w;
        int gbase = blk * ROWS_PER_BLK + base;
#pragma unroll
        for (int k = 0; k < TOPK; ++k) {
            float lb = dv[0]; int li = 0;
#pragma unroll
            for (int i = 1; i < 8; ++i)
                if (dv[i] < lb) { lb = dv[i]; li = i; }
            int gi = gbase + li;
            float wd = lb; int wi = gi;
#pragma unroll
            for (int off = 16; off; off >>= 1) {
                float od = __shfl_xor_sync(0xffffffffu, wd, off);
                int   oi = __shfl_xor_sync(0xffffffffu, wi, off);
                if (od < wd || (od == wd && oi < wi)) { wd = od; wi = oi; }
            }
            if (wi == gi) dv[li] = FMAX;
            if (lane == k) { g_cand_d[blk * 8 + k] = wd; g_cand_i[blk * 8 + k] = wi; }
        }
    }
    __syncthreads();
    __threadfence();
    if (tid == 0) atomicAdd(&g_arrive, 1u);
    if (blk != 0) return;

    // ================= GRID BARRIER (block 0 waits) =================
    if (tid == 0) {
        while (*(volatile unsigned*)&g_arrive < (unsigned)NBLK) { }
        *(volatile unsigned*)&g_arrive = 0u;   // reset for next graph replay
        __threadfence();
    }
    __syncthreads();   // B0

    // ================= PHASE B (block 0 only) =================
    int ff = tid >> 7, dd = tid & 127;
    int step = stepp[0];
    float epsw = 0.3f * expf(-(float)step / 200.0f);
    if (epsw < 0.05f) epsw = 0.05f;
    float epsn = epsw * 0.01f;
    bool debate = step > 5;
    int* nlist = (int*)pool;

    // fsum reduction (4 block-partials per faction) + init
    {
        float t = 0.f;
#pragma unroll
        for (int i = 0; i < 4; ++i) t += g_fpart[(ff * 4 + i) * HID + dd];
        fsum[ff][dd] = t;
        dsum[ff][dd] = 0.f;
    }
    if (tid < NFAC) cnt[tid] = 0;
    if (tid == 0) ncount = 0;

    // stage-2 selection: warp 0 over 256 candidates
    if (wid == 0) {
        float sv[8]; int iv[8];
#pragma unroll
        for (int i = 0; i < 8; ++i) {
            sv[i] = g_cand_d[lane * 8 + i];
            iv[i] = g_cand_i[lane * 8 + i];
        }
#pragma unroll
        for (int k = 0; k < TOPK; ++k) {
            float lb = sv[0]; int li = 0;
#pragma unroll
            for (int i = 1; i < 8; ++i)
                if (sv[i] < lb || (sv[i] == lb && iv[i] < iv[li])) { lb = sv[i]; li = i; }
            float wd = lb; int wi = iv[li];
#pragma unroll
            for (int off = 16; off; off >>= 1) {
                float od = __shfl_xor_sync(0xffffffffu, wd, off);
                int   oi = __shfl_xor_sync(0xffffffffu, wi, off);
                if (od < wd || (od == wd && oi < wi)) { wd = od; wi = oi; }
            }
            if (wi == iv[li]) sv[li] = FMAX;
            if (lane == k) { topd[k] = wd; topi[k] = wi; }
        }
    }
    __syncthreads();   // B1

    const int b1 = topi[0], b2 = topi[1];

    // top-8 proto row prefetch (independent of edge loads below)
    float pv_pref = proto[(size_t)topi[ff] * HID + dd];

    // edge/age row for b1: direct loads + neighbor mask/list
    {
        int j0 = tid * 8;
        const float4* er = (const float4*)(edges + (size_t)b1 * N_CELLS + j0);
        const float4* ar = (const float4*)(eages + (size_t)b1 * N_CELLS + j0);
        float4 e0 = er[0], e1 = er[1], a0 = ar[0], a1v = ar[1];
        float ev[8] = { e0.x, e0.y, e0.z, e0.w, e1.x, e1.y, e1.z, e1.w };
        float ag[8] = { a0.x, a0.y, a0.z, a0.w, a1v.x, a1v.y, a1v.z, a1v.w };
        unsigned char bits = 0;
#pragma unroll
        for (int i = 0; i < 8; ++i) {
            int j = j0 + i;
            float e = ev[i], a = ag[i];
            if (j == b2) { e = 1.f; a = 0.f; }
            a += 1.f;
            if (j == b1) a += 1.f;   // row add + col add both hit diagonal
            bool nm = (a <= 50.f) && (e > 0.f);
            if (nm) bits |= (unsigned char)(1 << i);
            if (nm && j != b1 && j != b2) {
                atomicAdd(&cnt[j >> 10], 1);
                int pos = atomicAdd(&ncount, 1);
                if (pos < NCAP) nlist[pos] = j;
                else {   // pathological overflow fallback (correct, slow)
                    const float* pr = proto + (size_t)j * HID;
                    for (int d = 0; d < HID; ++d) atomicAdd(&dsum[j >> 10][d], pr[d]);
                }
            }
        }
        nmask8[tid] = bits;
    }
    if (tid < TOPK) w8raw[tid] = expf(-(topd[tid] - topd[0]));
    sproto[ff][dd] = pv_pref;
    __syncthreads();   // B2

    // neighbor proto gather + bmu row updates
    {
        int n = ncount < NCAP ? ncount : NCAP;
        for (int e = ff; e < n; e += NFAC) {
            int j = nlist[e];
            atomicAdd(&dsum[j >> 10][dd], proto[(size_t)j * HID + dd]);
        }
    }
    if (tid < HID) {
        int d = tid;
        float s = ssig[d];
        bool m1 = (nmask8[b1 >> 3] >> (b1 & 7)) & 1;
        bool m2 = (nmask8[b2 >> 3] >> (b2 & 7)) & 1;
        float p1 = sproto[0][d];
        float v1 = p1 + epsw * (s - p1);
        if (m1) v1 = v1 + epsn * (s - v1);
        p1s[d] = v1;
        float p2 = sproto[1][d];
        float v2 = p2 + epsn * (s - p2);
        if (m2) v2 = v2 + epsn * (s - v2);
        p2s[d] = v2;
    }
    __syncthreads();   // B3

    // faction means: original sums + exact deltas
    {
        float adj = epsn * (ssig[dd] * (float)cnt[ff] - dsum[ff][dd]);
        if ((b1 >> 10) == ff) adj += p1s[dd] - sproto[0][dd];
        if ((b2 >> 10) == ff) adj += p2s[dd] - sproto[1][dd];
        fmean[ff][dd] = (fsum[ff][dd] + adj) * (1.0f / FS);
    }
    __syncthreads();   // B4

    // winner row (tids 0-127) + weighted combine (tids 128-255)
    if (tid < HID) {
        float g = 0.f;
#pragma unroll
        for (int f = 0; f < NFAC; ++f) g += fmean[f][tid];
        g *= (1.0f / NFAC);
        float v = 0.85f * p1s[tid] + 0.15f * fmean[b1 >> 10][tid];
        if (debate && (b1 & (FS - 1)) < 256) v = 0.85f * v + 0.15f * g;
        win[tid] = v;
    } else if (tid < 256) {
        int d = tid - 128;
        float g = 0.f;
#pragma unroll
        for (int f = 0; f < NFAC; ++f) g += fmean[f][d];
        g *= (1.0f / NFAC);
        float wsum = 0.f;
#pragma unroll
        for (int k = 0; k < TOPK; ++k) wsum += w8raw[k];
        float inv = 1.0f / wsum;
        float acc = 0.f;
#pragma unroll
        for (int k = 0; k < TOPK; ++k) {
            int i = topi[k];
            float pv;
            if (k == 0)      pv = p1s[d];
            else if (k == 1) pv = p2s[d];
            else {
                pv = sproto[k][d];
                if ((nmask8[i >> 3] >> (i & 7)) & 1) pv = pv + epsn * (ssig[d] - pv);
            }
            float v = 0.85f * pv + 0.15f * fmean[i >> 10][d];
            if (debate && (i & (FS - 1)) < 256) v = 0.85f * v + 0.15f * g;
            acc += w8raw[k] * v;
        }
        comb[d] = acc * inv;
    }
    __syncthreads();   // B5

    // MLP1: 256 outputs x 4 threads, direct LDG.128 weights
    {
        int o = tid >> 2, q = tid & 3;
        float bias = (o < 128) ? ea_b1[o] : eg_b1[o - 128];
        const float* wbase = (o < 128) ? (ea_w1 + o * HID) : (eg_w1 + (o - 128) * HID);
        const float4* w4 = (const float4*)(wbase + q * 32);
        const float4* v4 = (const float4*)(win + q * 32);
        float acc = 0.f;
#pragma unroll
        for (int i = 0; i < 8; ++i) {
            float4 a = w4[i], b = v4[i];
            acc += a.x * b.x + a.y * b.y + a.z * b.z + a.w * b.w;
        }
        acc += __shfl_down_sync(0xffffffffu, acc, 1);
        acc += __shfl_down_sync(0xffffffffu, acc, 2);
        if (q == 0) {
            float v = acc + bias;
            if (o < 128) h1[o] = v > 0.f ? v : 0.f;
            else         h2[o - 128] = v > 0.f ? v : 0.f;
        }
    }
    __syncthreads();   // B6

    // MLP2: tension (o<64, 2 dot products) + final output (o in 64..127)
    {
        int o = tid >> 2, q = tid & 3;
        float t = 0.f;
        if (o < 64) {
            float ba = ea_b2[o], bg = eg_b2[o];
            const float4* wa = (const float4*)(ea_w2 + o * HID + q * 32);
            const float4* wg = (const float4*)(eg_w2 + o * HID + q * 32);
            const float4* v1 = (const float4*)(h1 + q * 32);
            const float4* v2 = (const float4*)(h2 + q * 32);
            float a = 0.f, g = 0.f;
#pragma unroll
            for (int i = 0; i < 8; ++i) {
                float4 xa = wa[i], xg = wg[i], y1 = v1[i], y2 = v2[i];
                a += xa.x * y1.x + xa.y * y1.y + xa.z * y1.z + xa.w * y1.w;
                g += xg.x * y2.x + xg.y * y2.y + xg.z * y2.z + xg.w * y2.w;
            }
            a += __shfl_xor_sync(0xffffffffu, a, 1);
            a += __shfl_xor_sync(0xffffffffu, a, 2);
            g += __shfl_xor_sync(0xffffffffu, g, 1);
            g += __shfl_xor_sync(0xffffffffu, g, 2);
            if (q == 0) {
                float diff = (a + ba) - (g + bg);
                t = diff * diff;
            }
        } else if (o < 128) {
            int r = o - 64;
            float bo = out_b[r];
            const float4* wo = (const float4*)(out_w + r * HID + q * 32);
            const float4* c4 = (const float4*)(comb + q * 32);
            float acc = 0.f;
#pragma unroll
            for (int i = 0; i < 8; ++i) {
                float4 a = wo[i], b = c4[i];
                acc += a.x * b.x + a.y * b.y + a.z * b.z + a.w * b.w;
            }
            acc += __shfl_down_sync(0xffffffffu, acc, 1);
            acc += __shfl_down_sync(0xffffffffu, acc, 2);
            if (q == 0) out[r] = acc + bo;
        }
#pragma unroll
        for (int off = 16; off; off >>= 1)
            t += __shfl_down_sync(0xffffffffu, t, off);
        if (lane == 0 && wid < 8) rd[wid] = t;
    }
    __syncthreads();   // B7
    if (tid == 0) {
        float s = 0.f;
#pragma unroll
        for (int i = 0; i < 8; ++i) s += rd[i];
        out[OUT_DIM] = s * (1.0f / 64.0f);
    }
}

// ---------------------------------------------------------------------------
extern "C" void kernel_launch(void* const* d_in, const int* in_sizes, int n_in,
                              void* d_out, int out_size) {
    const float* x      = (const float*)d_in[0];
    const int*   step   = (const int*)  d_in[1];
    const float* proto  = (const float*)d_in[2];
    const float* edges  = (const float*)d_in[3];
    const float* eages  = (const float*)d_in[4];
    const float* in_w   = (const float*)d_in[5];
    const float* in_b   = (const float*)d_in[6];
    const float* out_w  = (const float*)d_in[7];
    const float* out_b  = (const float*)d_in[8];
    const float* ea_w1  = (const float*)d_in[9];
    const float* ea_b1  = (const float*)d_in[10];
    const float* ea_w2  = (const float*)d_in[11];
    const float* ea_b2  = (const float*)d_in[12];
    const float* eg_w1  = (const float*)d_in[13];
    const float* eg_b1  = (const float*)d_in[14];
    const float* eg_w2  = (const float*)d_in[15];
    const float* eg_b2  = (const float*)d_in[16];
    float* out = (float*)d_out;

    k_all<<<NBLK, 1024>>>(x, in_w, in_b, proto, edges, eages, step,
                          out_w, out_b,
                          ea_w1, ea_b1, ea_w2, ea_b2,
                          eg_w1, eg_b1, eg_w2, eg_b2,
                          out);
}